// round 1
// baseline (speedup 1.0000x reference)
#include <cuda_runtime.h>
#include <math.h>

// Problem constants
constexpr int Bc   = 2;
constexpr int Tc   = 2048;
constexpr int Dc   = 2048;
constexpr int Hc   = 32;
constexpr int HKVc = 8;
constexpr int DHc  = 64;
constexpr int BT   = Bc * Tc;          // 4096
constexpr int DKV  = HKVc * DHc;       // 512

// ---------------- scratch (__device__ globals, no allocation) ----------------
__device__ float g_qraw[BT * Dc];      // x @ Wq   [4096,2048]
__device__ float g_kraw[BT * DKV];     // x @ Wk   [4096,512]
__device__ float g_vraw[BT * DKV];     // x @ Wv   [4096,512]
__device__ float g_q  [BT * Dc];       // [B,H,T,DH] with RoPE
__device__ float g_k  [BT * DKV];      // [B,HKV,T,DH] with RoPE
__device__ float g_v  [BT * DKV];      // [B,HKV,T,DH]
__device__ float g_ctx[BT * Dc];       // [B,T,H*DH]

// ---------------- SGEMM: C[M,N] = A[M,K] @ B[K,N], row-major, exact tiles ----
template <int M, int N, int K>
__device__ __forceinline__ void sgemm_body(const float* __restrict__ A,
                                           const float* __restrict__ B,
                                           float* __restrict__ C) {
    constexpr int BM = 128, BN = 128, BK = 16;
    __shared__ __align__(16) float As[BK][BM];
    __shared__ __align__(16) float Bs[BK][BN];

    const int tid  = threadIdx.x;          // 256 threads
    const int brow = blockIdx.y * BM;
    const int bcol = blockIdx.x * BN;

    const int aRow = tid >> 2;             // 0..63
    const int aCol = (tid & 3) << 2;       // 0,4,8,12
    const int bRow = tid >> 5;             // 0..7
    const int bCol = (tid & 31) << 2;      // 0..124

    const int ty = tid >> 4;               // 0..15
    const int tx = tid & 15;               // 0..15

    float acc[8][8];
#pragma unroll
    for (int i = 0; i < 8; i++)
#pragma unroll
        for (int j = 0; j < 8; j++) acc[i][j] = 0.f;

    for (int k0 = 0; k0 < K; k0 += BK) {
#pragma unroll
        for (int i = 0; i < 2; i++) {
            const int r = aRow + i * 64;
            const float4 v = *reinterpret_cast<const float4*>(
                A + (size_t)(brow + r) * K + k0 + aCol);
            As[aCol + 0][r] = v.x;
            As[aCol + 1][r] = v.y;
            As[aCol + 2][r] = v.z;
            As[aCol + 3][r] = v.w;
        }
#pragma unroll
        for (int i = 0; i < 2; i++) {
            const int r = bRow + i * 8;
            *reinterpret_cast<float4*>(&Bs[r][bCol]) =
                *reinterpret_cast<const float4*>(
                    B + (size_t)(k0 + r) * N + bcol + bCol);
        }
        __syncthreads();

#pragma unroll
        for (int kk = 0; kk < BK; kk++) {
            float a[8], b[8];
            *reinterpret_cast<float4*>(&a[0]) =
                *reinterpret_cast<const float4*>(&As[kk][ty * 8]);
            *reinterpret_cast<float4*>(&a[4]) =
                *reinterpret_cast<const float4*>(&As[kk][ty * 8 + 4]);
            *reinterpret_cast<float4*>(&b[0]) =
                *reinterpret_cast<const float4*>(&Bs[kk][tx * 8]);
            *reinterpret_cast<float4*>(&b[4]) =
                *reinterpret_cast<const float4*>(&Bs[kk][tx * 8 + 4]);
#pragma unroll
            for (int i = 0; i < 8; i++)
#pragma unroll
                for (int j = 0; j < 8; j++) acc[i][j] += a[i] * b[j];
        }
        __syncthreads();
    }

#pragma unroll
    for (int i = 0; i < 8; i++) {
        float* Crow = C + (size_t)(brow + ty * 8 + i) * N + bcol + tx * 8;
        *reinterpret_cast<float4*>(Crow) =
            make_float4(acc[i][0], acc[i][1], acc[i][2], acc[i][3]);
        *reinterpret_cast<float4*>(Crow + 4) =
            make_float4(acc[i][4], acc[i][5], acc[i][6], acc[i][7]);
    }
}

__global__ __launch_bounds__(256) void k_qproj(const float* __restrict__ x,
                                               const float* __restrict__ W) {
    sgemm_body<BT, Dc, Dc>(x, W, g_qraw);
}
__global__ __launch_bounds__(256) void k_kproj(const float* __restrict__ x,
                                               const float* __restrict__ W) {
    sgemm_body<BT, DKV, Dc>(x, W, g_kraw);
}
__global__ __launch_bounds__(256) void k_vproj(const float* __restrict__ x,
                                               const float* __restrict__ W) {
    sgemm_body<BT, DKV, Dc>(x, W, g_vraw);
}
__global__ __launch_bounds__(256) void k_oproj(const float* __restrict__ W,
                                               float* __restrict__ out) {
    sgemm_body<BT, Dc, Dc>(g_ctx, W, out);
}

// ---------------- RoPE + layout transforms -----------------------------------
// ln(10000)/32
#define ROPE_LN_C 0.28782313662425575f

__global__ __launch_bounds__(256) void rope_q_kernel() {
    const int idx = blockIdx.x * 256 + threadIdx.x;   // over [B,H,T,DH]
    const int d = idx & 63;
    const int t = (idx >> 6) & 2047;
    const int h = (idx >> 17) & 31;
    const int b = idx >> 22;
    const size_t row = (size_t)(b * Tc + t) * Dc + h * DHc;
    const float raw  = g_qraw[row + d];
    const float pair = g_qraw[row + ((d < 32) ? d + 32 : d - 32)];
    const float rot  = (d < 32) ? -pair : pair;
    const int   i    = d & 31;
    const float invf = expf(-(float)i * ROPE_LN_C);
    const float ang  = (float)t * invf;
    g_q[idx] = raw * cosf(ang) + rot * sinf(ang);
}

__global__ __launch_bounds__(256) void rope_k_kernel() {
    const int idx = blockIdx.x * 256 + threadIdx.x;   // over [B,HKV,T,DH]
    const int d  = idx & 63;
    const int t  = (idx >> 6) & 2047;
    const int kv = (idx >> 17) & 7;
    const int b  = idx >> 20;
    const size_t row = (size_t)(b * Tc + t) * DKV + kv * DHc;
    const float raw  = g_kraw[row + d];
    const float pair = g_kraw[row + ((d < 32) ? d + 32 : d - 32)];
    const float rot  = (d < 32) ? -pair : pair;
    const int   i    = d & 31;
    const float invf = expf(-(float)i * ROPE_LN_C);
    const float ang  = (float)t * invf;
    g_k[idx] = raw * cosf(ang) + rot * sinf(ang);
}

__global__ __launch_bounds__(256) void copy_v_kernel() {
    const int idx = blockIdx.x * 256 + threadIdx.x;   // over [B,HKV,T,DH]
    const int d  = idx & 63;
    const int t  = (idx >> 6) & 2047;
    const int kv = (idx >> 17) & 7;
    const int b  = idx >> 20;
    g_v[idx] = g_vraw[(size_t)(b * Tc + t) * DKV + kv * DHc + d];
}

// ---------------- Causal flash attention (fp32, online softmax) --------------
// grid: (T/64, H, B), block: 256
__global__ __launch_bounds__(256) void attn_kernel() {
    constexpr int BQ = 64, BKT = 32, DHP = 68, SSP = 36;
    __shared__ __align__(16) float Qs[BQ][DHP];
    __shared__ __align__(16) float Ks[BKT][DHP];
    __shared__ __align__(16) float Vs[BKT][DHP];
    __shared__ __align__(16) float Ss[BQ][SSP];
    __shared__ float m_s[BQ], l_s[BQ], corr_s[BQ];

    const int tid = threadIdx.x;
    const int qt  = blockIdx.x;
    const int h   = blockIdx.y;
    const int b   = blockIdx.z;
    const int kv  = h >> 2;   // h // G

    const float* Qp = g_q + ((size_t)(b * Hc + h) * Tc + qt * BQ) * DHc;
    const float* Kp = g_k + (size_t)(b * HKVc + kv) * Tc * DHc;
    const float* Vp = g_v + (size_t)(b * HKVc + kv) * Tc * DHc;

    // load Q tile (64x64), float4
    for (int i = tid; i < BQ * DHc / 4; i += 256) {
        const int r = i >> 4;
        const int c = (i & 15) << 2;
        *reinterpret_cast<float4*>(&Qs[r][c]) =
            *reinterpret_cast<const float4*>(Qp + r * DHc + c);
    }
    if (tid < BQ) { m_s[tid] = -1e30f; l_s[tid] = 0.f; }

    float o[4][4];
#pragma unroll
    for (int i = 0; i < 4; i++)
#pragma unroll
        for (int j = 0; j < 4; j++) o[i][j] = 0.f;

    const int qr0  = (tid >> 4) * 4;   // 4 query rows
    const int dc0  = (tid & 15) * 4;   // 4 output dims
    const int kc0  = (tid & 15) * 2;   // 2 key cols for S phase
    const int ntiles = 2 * qt + 2;     // causal: keys 0 .. qt*64+63

    __syncthreads();

    for (int kt = 0; kt < ntiles; kt++) {
        const int kbase = kt * BKT;
        // load K,V tiles (32x64 each)
        for (int i = tid; i < BKT * DHc / 4; i += 256) {
            const int r = i >> 4;
            const int c = (i & 15) << 2;
            *reinterpret_cast<float4*>(&Ks[r][c]) =
                *reinterpret_cast<const float4*>(Kp + (size_t)(kbase + r) * DHc + c);
            *reinterpret_cast<float4*>(&Vs[r][c]) =
                *reinterpret_cast<const float4*>(Vp + (size_t)(kbase + r) * DHc + c);
        }
        __syncthreads();

        // S = Q K^T for this thread's 4x2 patch
        float s[4][2] = {{0.f, 0.f}, {0.f, 0.f}, {0.f, 0.f}, {0.f, 0.f}};
#pragma unroll
        for (int d = 0; d < DHc; d += 4) {
            float4 ka = *reinterpret_cast<const float4*>(&Ks[kc0 + 0][d]);
            float4 kb = *reinterpret_cast<const float4*>(&Ks[kc0 + 1][d]);
#pragma unroll
            for (int i = 0; i < 4; i++) {
                float4 q = *reinterpret_cast<const float4*>(&Qs[qr0 + i][d]);
                s[i][0] += q.x * ka.x + q.y * ka.y + q.z * ka.z + q.w * ka.w;
                s[i][1] += q.x * kb.x + q.y * kb.y + q.z * kb.z + q.w * kb.w;
            }
        }
        // mask + scale, store to smem
#pragma unroll
        for (int i = 0; i < 4; i++) {
            const int qi = qt * BQ + qr0 + i;
#pragma unroll
            for (int j = 0; j < 2; j++) {
                const int kj = kbase + kc0 + j;
                Ss[qr0 + i][kc0 + j] = (kj <= qi) ? s[i][j] * 0.125f : -1e30f;
            }
        }
        __syncthreads();

        // per-row online softmax (one thread per row)
        if (tid < BQ) {
            const float mold = m_s[tid];
            float mmax = mold;
#pragma unroll
            for (int c = 0; c < BKT; c++) mmax = fmaxf(mmax, Ss[tid][c]);
            const float cr = __expf(mold - mmax);
            float lsum = 0.f;
#pragma unroll
            for (int c = 0; c < BKT; c++) {
                const float e = __expf(Ss[tid][c] - mmax);
                Ss[tid][c] = e;
                lsum += e;
            }
            m_s[tid]   = mmax;
            l_s[tid]   = l_s[tid] * cr + lsum;
            corr_s[tid] = cr;
        }
        __syncthreads();

        // rescale O, accumulate P @ V
        {
            float cr[4];
#pragma unroll
            for (int i = 0; i < 4; i++) cr[i] = corr_s[qr0 + i];
#pragma unroll
            for (int i = 0; i < 4; i++)
#pragma unroll
                for (int j = 0; j < 4; j++) o[i][j] *= cr[i];
        }
#pragma unroll
        for (int kc = 0; kc < BKT; kc += 4) {
            float4 v0 = *reinterpret_cast<const float4*>(&Vs[kc + 0][dc0]);
            float4 v1 = *reinterpret_cast<const float4*>(&Vs[kc + 1][dc0]);
            float4 v2 = *reinterpret_cast<const float4*>(&Vs[kc + 2][dc0]);
            float4 v3 = *reinterpret_cast<const float4*>(&Vs[kc + 3][dc0]);
#pragma unroll
            for (int i = 0; i < 4; i++) {
                float4 p = *reinterpret_cast<const float4*>(&Ss[qr0 + i][kc]);
                o[i][0] += p.x * v0.x + p.y * v1.x + p.z * v2.x + p.w * v3.x;
                o[i][1] += p.x * v0.y + p.y * v1.y + p.z * v2.y + p.w * v3.y;
                o[i][2] += p.x * v0.z + p.y * v1.z + p.z * v2.z + p.w * v3.z;
                o[i][3] += p.x * v0.w + p.y * v1.w + p.z * v2.w + p.w * v3.w;
            }
        }
        __syncthreads();
    }

    // normalize and write ctx[b][t][h*DH + d]
#pragma unroll
    for (int i = 0; i < 4; i++) {
        const float inv = 1.f / l_s[qr0 + i];
        const size_t off =
            (size_t)(b * Tc + qt * BQ + qr0 + i) * Dc + h * DHc + dc0;
        *reinterpret_cast<float4*>(g_ctx + off) =
            make_float4(o[i][0] * inv, o[i][1] * inv, o[i][2] * inv, o[i][3] * inv);
    }
}

// ---------------- launch ------------------------------------------------------
extern "C" void kernel_launch(void* const* d_in, const int* in_sizes, int n_in,
                              void* d_out, int out_size) {
    const float* x  = (const float*)d_in[0];
    const float* Wq = (const float*)d_in[1];
    const float* Wk = (const float*)d_in[2];
    const float* Wv = (const float*)d_in[3];
    const float* Wo = (const float*)d_in[4];
    float* out = (float*)d_out;

    k_qproj<<<dim3(Dc / 128, BT / 128), 256>>>(x, Wq);
    k_kproj<<<dim3(DKV / 128, BT / 128), 256>>>(x, Wk);
    k_vproj<<<dim3(DKV / 128, BT / 128), 256>>>(x, Wv);

    rope_q_kernel<<<(BT * Dc) / 256, 256>>>();
    rope_k_kernel<<<(BT * DKV) / 256, 256>>>();
    copy_v_kernel<<<(BT * DKV) / 256, 256>>>();

    attn_kernel<<<dim3(Tc / 64, Hc, Bc), 256>>>();

    k_oproj<<<dim3(Dc / 128, BT / 128), 256>>>(Wo, out);
}

// round 6
// speedup vs baseline: 1.3685x; 1.3685x over previous
#include <cuda_runtime.h>
#include <cuda_bf16.h>
#include <mma.h>
#include <math.h>

using namespace nvcuda;

// Problem constants
constexpr int Bc   = 2;
constexpr int Tc   = 2048;
constexpr int Dc   = 2048;
constexpr int Hc   = 32;
constexpr int HKVc = 8;
constexpr int DHc  = 64;
constexpr int BT   = Bc * Tc;          // 4096
constexpr int DKV  = HKVc * DHc;       // 512

// ---------------- scratch (__device__ globals, no allocation) ----------------
// NOTE: only ever referenced from DEVICE code (never passed from host).
__device__ float g_qraw[BT * Dc];
__device__ float g_kraw[BT * DKV];
__device__ float g_vraw[BT * DKV];
__device__ float g_q  [BT * Dc];       // [B,H,T,DH] with RoPE
__device__ float g_k  [BT * DKV];      // [B,HKV,T,DH] with RoPE
__device__ float g_v  [BT * DKV];      // [B,HKV,T,DH]
__device__ float g_ctx[BT * Dc];       // [B,T,H*DH]

// ---------------- helpers -----------------------------------------------------
__device__ __forceinline__ void split4(const float4 v,
                                       __nv_bfloat16* hi, __nv_bfloat16* lo) {
    const __nv_bfloat16 hx = __float2bfloat16_rn(v.x);
    const __nv_bfloat16 hy = __float2bfloat16_rn(v.y);
    const __nv_bfloat16 hz = __float2bfloat16_rn(v.z);
    const __nv_bfloat16 hw = __float2bfloat16_rn(v.w);
    __nv_bfloat162* h2 = reinterpret_cast<__nv_bfloat162*>(hi);
    __nv_bfloat162* l2 = reinterpret_cast<__nv_bfloat162*>(lo);
    h2[0] = __halves2bfloat162(hx, hy);
    h2[1] = __halves2bfloat162(hz, hw);
    l2[0] = __halves2bfloat162(__float2bfloat16_rn(v.x - __bfloat162float(hx)),
                               __float2bfloat16_rn(v.y - __bfloat162float(hy)));
    l2[1] = __halves2bfloat162(__float2bfloat16_rn(v.z - __bfloat162float(hz)),
                               __float2bfloat16_rn(v.w - __bfloat162float(hw)));
}

// ---------------- bf16x3 split GEMM via wmma (device body) -------------------
// C[4096, N] = A[4096, 2048] @ B[2048, N], all fp32 row-major.
// block = 256 (8 warps: 4 along M x 2 along N), CTA tile 128x128, BK=32.
template <int N>
__device__ __forceinline__ void mma_gemm_body(const float* __restrict__ A,
                                              const float* __restrict__ B,
                                              float* __restrict__ C) {
    constexpr int K  = 2048;
    constexpr int BM = 128, BN = 128, BK = 32;
    constexpr int ASTR = BK + 8;   // 40 bf16 = 80 B per row
    constexpr int BSTR = BN + 8;   // 136 bf16 = 272 B per row

    __shared__ __align__(32) __nv_bfloat16 Ah[BM][ASTR];
    __shared__ __align__(32) __nv_bfloat16 Al[BM][ASTR];
    __shared__ __align__(32) __nv_bfloat16 Bh[BK][BSTR];
    __shared__ __align__(32) __nv_bfloat16 Bl[BK][BSTR];

    const int tid  = threadIdx.x;
    const int warp = tid >> 5;
    const int wm   = (warp >> 1) * 32;   // warp row origin in tile
    const int wn   = (warp & 1) * 64;    // warp col origin in tile
    const int brow = blockIdx.y * BM;
    const int bcol = blockIdx.x * BN;

    const int ar = tid >> 3;             // 0..31 (A row, step 32)
    const int ac = (tid & 7) * 4;        // 0..28 (A col)
    const int bk = tid >> 5;             // 0..7  (B k-row, step 8)
    const int bn = (tid & 31) * 4;       // 0..124 (B col)

    wmma::fragment<wmma::accumulator, 16, 16, 16, float> acc[2][4];
#pragma unroll
    for (int mi = 0; mi < 2; mi++) {
#pragma unroll
        for (int nj = 0; nj < 4; nj++) {
            wmma::fill_fragment(acc[mi][nj], 0.0f);
        }
    }

    float4 aReg[4];
    float4 bReg[4];
#pragma unroll
    for (int i = 0; i < 4; i++) {
        aReg[i] = *reinterpret_cast<const float4*>(A + (size_t)(brow + ar + i * 32) * K + ac);
        bReg[i] = *reinterpret_cast<const float4*>(B + (size_t)(bk + i * 8) * N + bcol + bn);
    }

    for (int kt = 0; kt < K / BK; kt++) {
#pragma unroll
        for (int i = 0; i < 4; i++) {
            const int r = ar + i * 32;
            split4(aReg[i], &Ah[r][ac], &Al[r][ac]);
            const int rb = bk + i * 8;
            split4(bReg[i], &Bh[rb][bn], &Bl[rb][bn]);
        }
        __syncthreads();

        if (kt + 1 < K / BK) {
            const int k0 = (kt + 1) * BK;
#pragma unroll
            for (int i = 0; i < 4; i++) {
                aReg[i] = *reinterpret_cast<const float4*>(
                    A + (size_t)(brow + ar + i * 32) * K + k0 + ac);
                bReg[i] = *reinterpret_cast<const float4*>(
                    B + (size_t)(k0 + bk + i * 8) * N + bcol + bn);
            }
        }

#pragma unroll
        for (int ks = 0; ks < 2; ks++) {
            wmma::fragment<wmma::matrix_a, 16, 16, 16, __nv_bfloat16, wmma::row_major> fAh[2];
            wmma::fragment<wmma::matrix_a, 16, 16, 16, __nv_bfloat16, wmma::row_major> fAl[2];
#pragma unroll
            for (int mi = 0; mi < 2; mi++) {
                wmma::load_matrix_sync(fAh[mi], &Ah[wm + mi * 16][ks * 16], ASTR);
                wmma::load_matrix_sync(fAl[mi], &Al[wm + mi * 16][ks * 16], ASTR);
            }
#pragma unroll
            for (int nj = 0; nj < 4; nj++) {
                wmma::fragment<wmma::matrix_b, 16, 16, 16, __nv_bfloat16, wmma::row_major> fBh;
                wmma::fragment<wmma::matrix_b, 16, 16, 16, __nv_bfloat16, wmma::row_major> fBl;
                wmma::load_matrix_sync(fBh, &Bh[ks * 16][wn + nj * 16], BSTR);
                wmma::load_matrix_sync(fBl, &Bl[ks * 16][wn + nj * 16], BSTR);
#pragma unroll
                for (int mi = 0; mi < 2; mi++) {
                    wmma::mma_sync(acc[mi][nj], fAh[mi], fBh, acc[mi][nj]);
                    wmma::mma_sync(acc[mi][nj], fAh[mi], fBl, acc[mi][nj]);
                    wmma::mma_sync(acc[mi][nj], fAl[mi], fBh, acc[mi][nj]);
                }
            }
        }
        __syncthreads();
    }

#pragma unroll
    for (int mi = 0; mi < 2; mi++) {
#pragma unroll
        for (int nj = 0; nj < 4; nj++) {
            float* p = C + (size_t)(brow + wm + mi * 16) * N + bcol + wn + nj * 16;
            wmma::store_matrix_sync(p, acc[mi][nj], N, wmma::mem_row_major);
        }
    }
}

// Wrappers: scratch globals referenced from DEVICE code only.
__global__ __launch_bounds__(256) void k_qproj(const float* __restrict__ x,
                                               const float* __restrict__ W) {
    mma_gemm_body<Dc>(x, W, g_qraw);
}
__global__ __launch_bounds__(256) void k_kproj(const float* __restrict__ x,
                                               const float* __restrict__ W) {
    mma_gemm_body<DKV>(x, W, g_kraw);
}
__global__ __launch_bounds__(256) void k_vproj(const float* __restrict__ x,
                                               const float* __restrict__ W) {
    mma_gemm_body<DKV>(x, W, g_vraw);
}
__global__ __launch_bounds__(256) void k_oproj(const float* __restrict__ W,
                                               float* __restrict__ out) {
    mma_gemm_body<Dc>(g_ctx, W, out);
}

// ---------------- RoPE + layout transforms -----------------------------------
#define ROPE_LN_C 0.28782313662425575f

__global__ __launch_bounds__(256) void rope_q_kernel() {
    const int idx = blockIdx.x * 256 + threadIdx.x;   // over [B,H,T,DH]
    const int d = idx & 63;
    const int t = (idx >> 6) & 2047;
    const int h = (idx >> 17) & 31;
    const int b = idx >> 22;
    const size_t row = (size_t)(b * Tc + t) * Dc + h * DHc;
    const float raw  = g_qraw[row + d];
    const float pair = g_qraw[row + ((d < 32) ? d + 32 : d - 32)];
    const float rot  = (d < 32) ? -pair : pair;
    const int   i    = d & 31;
    const float invf = expf(-(float)i * ROPE_LN_C);
    const float ang  = (float)t * invf;
    g_q[idx] = raw * cosf(ang) + rot * sinf(ang);
}

__global__ __launch_bounds__(256) void rope_k_kernel() {
    const int idx = blockIdx.x * 256 + threadIdx.x;   // over [B,HKV,T,DH]
    const int d  = idx & 63;
    const int t  = (idx >> 6) & 2047;
    const int kv = (idx >> 17) & 7;
    const int b  = idx >> 20;
    const size_t row = (size_t)(b * Tc + t) * DKV + kv * DHc;
    const float raw  = g_kraw[row + d];
    const float pair = g_kraw[row + ((d < 32) ? d + 32 : d - 32)];
    const float rot  = (d < 32) ? -pair : pair;
    const int   i    = d & 31;
    const float invf = expf(-(float)i * ROPE_LN_C);
    const float ang  = (float)t * invf;
    g_k[idx] = raw * cosf(ang) + rot * sinf(ang);
}

__global__ __launch_bounds__(256) void copy_v_kernel() {
    const int idx = blockIdx.x * 256 + threadIdx.x;   // over [B,HKV,T,DH]
    const int d  = idx & 63;
    const int t  = (idx >> 6) & 2047;
    const int kv = (idx >> 17) & 7;
    const int b  = idx >> 20;
    g_v[idx] = g_vraw[(size_t)(b * Tc + t) * DKV + kv * DHc + d];
}

// ---------------- Causal flash attention (fp32, online softmax) --------------
// grid: (T/64, H, B), block: 256
__global__ __launch_bounds__(256) void attn_kernel() {
    constexpr int BQ = 64, BKT = 32, DHP = 68, SSP = 36;
    __shared__ __align__(16) float Qs[BQ][DHP];
    __shared__ __align__(16) float Ks[BKT][DHP];
    __shared__ __align__(16) float Vs[BKT][DHP];
    __shared__ __align__(16) float Ss[BQ][SSP];
    __shared__ float m_s[BQ], l_s[BQ], corr_s[BQ];

    const int tid = threadIdx.x;
    const int qt  = blockIdx.x;
    const int h   = blockIdx.y;
    const int b   = blockIdx.z;
    const int kv  = h >> 2;

    const float* Qp = g_q + ((size_t)(b * Hc + h) * Tc + qt * BQ) * DHc;
    const float* Kp = g_k + (size_t)(b * HKVc + kv) * Tc * DHc;
    const float* Vp = g_v + (size_t)(b * HKVc + kv) * Tc * DHc;

    for (int i = tid; i < BQ * DHc / 4; i += 256) {
        const int r = i >> 4;
        const int c = (i & 15) << 2;
        *reinterpret_cast<float4*>(&Qs[r][c]) =
            *reinterpret_cast<const float4*>(Qp + r * DHc + c);
    }
    if (tid < BQ) { m_s[tid] = -1e30f; l_s[tid] = 0.f; }

    float o[4][4];
#pragma unroll
    for (int i = 0; i < 4; i++) {
#pragma unroll
        for (int j = 0; j < 4; j++) { o[i][j] = 0.f; }
    }

    const int qr0  = (tid >> 4) * 4;
    const int dc0  = (tid & 15) * 4;
    const int kc0  = (tid & 15) * 2;
    const int ntiles = 2 * qt + 2;

    __syncthreads();

    for (int kt = 0; kt < ntiles; kt++) {
        const int kbase = kt * BKT;
        for (int i = tid; i < BKT * DHc / 4; i += 256) {
            const int r = i >> 4;
            const int c = (i & 15) << 2;
            *reinterpret_cast<float4*>(&Ks[r][c]) =
                *reinterpret_cast<const float4*>(Kp + (size_t)(kbase + r) * DHc + c);
            *reinterpret_cast<float4*>(&Vs[r][c]) =
                *reinterpret_cast<const float4*>(Vp + (size_t)(kbase + r) * DHc + c);
        }
        __syncthreads();

        float s[4][2] = {{0.f, 0.f}, {0.f, 0.f}, {0.f, 0.f}, {0.f, 0.f}};
#pragma unroll
        for (int d = 0; d < DHc; d += 4) {
            float4 ka = *reinterpret_cast<const float4*>(&Ks[kc0 + 0][d]);
            float4 kb = *reinterpret_cast<const float4*>(&Ks[kc0 + 1][d]);
#pragma unroll
            for (int i = 0; i < 4; i++) {
                float4 q = *reinterpret_cast<const float4*>(&Qs[qr0 + i][d]);
                s[i][0] += q.x * ka.x + q.y * ka.y + q.z * ka.z + q.w * ka.w;
                s[i][1] += q.x * kb.x + q.y * kb.y + q.z * kb.z + q.w * kb.w;
            }
        }
#pragma unroll
        for (int i = 0; i < 4; i++) {
            const int qi = qt * BQ + qr0 + i;
#pragma unroll
            for (int j = 0; j < 2; j++) {
                const int kj = kbase + kc0 + j;
                Ss[qr0 + i][kc0 + j] = (kj <= qi) ? s[i][j] * 0.125f : -1e30f;
            }
        }
        __syncthreads();

        if (tid < BQ) {
            const float mold = m_s[tid];
            float mmax = mold;
#pragma unroll
            for (int c = 0; c < BKT; c++) { mmax = fmaxf(mmax, Ss[tid][c]); }
            const float cr = __expf(mold - mmax);
            float lsum = 0.f;
#pragma unroll
            for (int c = 0; c < BKT; c++) {
                const float e = __expf(Ss[tid][c] - mmax);
                Ss[tid][c] = e;
                lsum += e;
            }
            m_s[tid]    = mmax;
            l_s[tid]    = l_s[tid] * cr + lsum;
            corr_s[tid] = cr;
        }
        __syncthreads();

        float cr[4];
#pragma unroll
        for (int i = 0; i < 4; i++) { cr[i] = corr_s[qr0 + i]; }
#pragma unroll
        for (int i = 0; i < 4; i++) {
#pragma unroll
            for (int j = 0; j < 4; j++) { o[i][j] *= cr[i]; }
        }
#pragma unroll
        for (int kc = 0; kc < BKT; kc += 4) {
            float4 v0 = *reinterpret_cast<const float4*>(&Vs[kc + 0][dc0]);
            float4 v1 = *reinterpret_cast<const float4*>(&Vs[kc + 1][dc0]);
            float4 v2 = *reinterpret_cast<const float4*>(&Vs[kc + 2][dc0]);
            float4 v3 = *reinterpret_cast<const float4*>(&Vs[kc + 3][dc0]);
#pragma unroll
            for (int i = 0; i < 4; i++) {
                float4 p = *reinterpret_cast<const float4*>(&Ss[qr0 + i][kc]);
                o[i][0] += p.x * v0.x + p.y * v1.x + p.z * v2.x + p.w * v3.x;
                o[i][1] += p.x * v0.y + p.y * v1.y + p.z * v2.y + p.w * v3.y;
                o[i][2] += p.x * v0.z + p.y * v1.z + p.z * v2.z + p.w * v3.z;
                o[i][3] += p.x * v0.w + p.y * v1.w + p.z * v2.w + p.w * v3.w;
            }
        }
        __syncthreads();
    }

#pragma unroll
    for (int i = 0; i < 4; i++) {
        const float inv = 1.f / l_s[qr0 + i];
        const size_t off =
            (size_t)(b * Tc + qt * BQ + qr0 + i) * Dc + h * DHc + dc0;
        *reinterpret_cast<float4*>(g_ctx + off) =
            make_float4(o[i][0] * inv, o[i][1] * inv, o[i][2] * inv, o[i][3] * inv);
    }
}

// ---------------- launch ------------------------------------------------------
extern "C" void kernel_launch(void* const* d_in, const int* in_sizes, int n_in,
                              void* d_out, int out_size) {
    const float* x  = (const float*)d_in[0];
    const float* Wq = (const float*)d_in[1];
    const float* Wk = (const float*)d_in[2];
    const float* Wv = (const float*)d_in[3];
    const float* Wo = (const float*)d_in[4];
    float* out = (float*)d_out;

    dim3 gridBig(Dc / 128, BT / 128);
    dim3 gridKV(DKV / 128, BT / 128);

    k_qproj<<<gridBig, 256>>>(x, Wq);
    k_kproj<<<gridKV, 256>>>(x, Wk);
    k_vproj<<<gridKV, 256>>>(x, Wv);

    rope_q_kernel<<<(BT * Dc) / 256, 256>>>();
    rope_k_kernel<<<(BT * DKV) / 256, 256>>>();
    copy_v_kernel<<<(BT * DKV) / 256, 256>>>();

    attn_kernel<<<dim3(Tc / 64, Hc, Bc), 256>>>();

    k_oproj<<<gridBig, 256>>>(Wo, out);
}